// round 10
// baseline (speedup 1.0000x reference)
#include <cuda_runtime.h>
#include <cuda_bf16.h>

#define N_NODES 10000
#define N_EDGES 640000
#define D 128

// ---- scratch (no device allocations allowed) ----
__device__ int g_deg[N_NODES];
__device__ int g_off[N_NODES + 1];
__device__ int g_rank[N_EDGES];
__device__ int g_src_sorted[N_EDGES];
__device__ int g_work;

// ---- f32x2 packed helpers (sm_10x; ptxas won't emit these from C++) ----
__device__ __forceinline__ void fadd2(unsigned long long& acc, unsigned long long v) {
    asm("add.rn.f32x2 %0, %0, %1;" : "+l"(acc) : "l"(v));
}
__device__ __forceinline__ void ffma2(unsigned long long& acc,
                                      unsigned long long a, unsigned long long b) {
    asm("fma.rn.f32x2 %0, %1, %2, %0;" : "+l"(acc) : "l"(a), "l"(b));
}
__device__ __forceinline__ unsigned long long pack2(float h) {
    unsigned long long r;
    asm("mov.b64 %0, {%1, %1};" : "=l"(r) : "f"(h));
    return r;
}

// ---------------------------------------------------------------------------
// 1) zero degree histogram + work counter + sentinel
__global__ void zero_deg_kernel() {
    int i = blockIdx.x * blockDim.x + threadIdx.x;
    if (i < N_NODES) g_deg[i] = 0;
    if (i == 0) { g_off[N_NODES] = N_EDGES; g_work = 0; }
}

// 2) histogram of dst WITH per-edge rank. ILP 2, 320K threads.
__global__ void rank_hist_kernel(const int* __restrict__ dst) {
    const int T = N_EDGES / 2;
    int t = blockIdx.x * blockDim.x + threadIdx.x;
    if (t >= T) return;
    int2 d2 = ((const int2*)dst)[t];
    int r0 = atomicAdd(&g_deg[d2.x], 1);
    int r1 = atomicAdd(&g_deg[d2.y], 1);
    ((int2*)g_rank)[t] = make_int2(r0, r1);
}

// 3) single-block exclusive scan (shuffle-based)
__global__ void scan_kernel() {
    __shared__ int warp_sums[32];
    const int t = threadIdx.x;
    const int lane = t & 31, w = t >> 5;
    const int CHUNK = (N_NODES + 1023) / 1024;  // 10
    const int base = t * CHUNK;

    int deg[CHUNK];
    int s = 0;
    #pragma unroll
    for (int i = 0; i < CHUNK; i++) {
        int n = base + i;
        deg[i] = (n < N_NODES) ? g_deg[n] : 0;
        s += deg[i];
    }
    int incl = s;
    #pragma unroll
    for (int d = 1; d < 32; d <<= 1) {
        int v = __shfl_up_sync(0xffffffffu, incl, d);
        if (lane >= d) incl += v;
    }
    if (lane == 31) warp_sums[w] = incl;
    __syncthreads();
    if (w == 0) {
        int iv = warp_sums[lane];
        #pragma unroll
        for (int d = 1; d < 32; d <<= 1) {
            int u = __shfl_up_sync(0xffffffffu, iv, d);
            if (lane >= d) iv += u;
        }
        warp_sums[lane] = iv;
    }
    __syncthreads();
    int run = ((w > 0) ? warp_sums[w - 1] : 0) + (incl - s);
    #pragma unroll
    for (int i = 0; i < CHUNK; i++) {
        int n = base + i;
        if (n < N_NODES) {
            g_off[n] = run;
            run += deg[i];
        }
    }
}

// 4) scatter edges — no atomics: pos = off[dst] + rank. ILP 2.
__global__ void scatter_kernel(const int* __restrict__ src,
                               const int* __restrict__ dst) {
    const int T = N_EDGES / 2;
    int t = blockIdx.x * blockDim.x + threadIdx.x;
    if (t >= T) return;
    int2 s2 = ((const int2*)src)[t];
    int2 d2 = ((const int2*)dst)[t];
    int2 r2 = ((const int2*)g_rank)[t];
    int o0 = __ldg(&g_off[d2.x]);
    int o1 = __ldg(&g_off[d2.y]);
    g_src_sorted[o0 + r2.x] = s2.x;
    g_src_sorted[o1 + r2.y] = s2.y;
}

// ---------------------------------------------------------------------------
// 5) fused gather+projection. 1024-thread blocks (32 warps share ONE sW copy)
//    -> 84KB smem/block -> 2 blocks/SM -> 64 warps/SM. Work unit = 1 node,
//    warp-level work stealing; gather interleaves two 32-edge chunks for MLP.
#define SW_STRIDE 132
#define SW_FLOATS (D * SW_STRIDE)                  // 16896
#define SH_FLOATS (32 * D)                         // 32 warps x 128
#define SMEM_BYTES ((SW_FLOATS + SH_FLOATS) * 4)   // 83968 B

__device__ __forceinline__ int steal(int lane) {
    int p = 0;
    if (lane == 0) p = atomicAdd(&g_work, 1);
    return __shfl_sync(0xffffffffu, p, 0);
}

// consume one 32-edge chunk (indices in idx) into a0/a1
__device__ __forceinline__ void consume_chunk(const float* __restrict__ x,
                                              int idx, int lane,
                                              unsigned long long* a0,
                                              unsigned long long* a1) {
    #pragma unroll
    for (int j = 0; j < 32; j += 2) {
        int s0 = __shfl_sync(0xffffffffu, idx, j);
        int s1 = __shfl_sync(0xffffffffu, idx, j + 1);
        ulonglong2 v0 = *(const ulonglong2*)&x[s0 * D + 4 * lane];
        ulonglong2 v1 = *(const ulonglong2*)&x[s1 * D + 4 * lane];
        fadd2(a0[0], v0.x); fadd2(a0[1], v0.y);
        fadd2(a1[0], v1.x); fadd2(a1[1], v1.y);
    }
}

__global__ __launch_bounds__(1024, 2)
void fused_agg_proj_kernel(const float* __restrict__ x,
                           const float* __restrict__ W,
                           const float* __restrict__ b,
                           float* __restrict__ out) {
    extern __shared__ float smem[];
    float* sW = smem;                  // [128][132] transposed W (shared by 32 warps)
    float* sh = smem + SW_FLOATS;      // [32 warps][128] h rows

    const int tid  = threadIdx.x;
    const int lane = tid & 31;
    const int wid  = tid >> 5;

    // stage W transposed (coalesced gmem reads), all 1024 threads
    for (int idx = tid; idx < D * D; idx += 1024) {
        int o = idx >> 7;
        int i = idx & 127;
        sW[i * SW_STRIDE + o] = W[idx];
    }
    __syncthreads();

    float* hbuf = &sh[wid * D];
    const ulonglong2 bb = *(const ulonglong2*)&b[4 * lane];

    int n = steal(lane);
    while (n < N_NODES) {
        int next = steal(lane);                 // prefetch next unit

        const int e0 = __ldg(&g_off[n]);
        const int e1 = __ldg(&g_off[n + 1]);
        const int deg = e1 - e0;
        const int nc  = deg >> 5;               // full 32-edge chunks

        unsigned long long a0[2] = {0ull, 0ull}, a1[2] = {0ull, 0ull};
        unsigned long long a2[2] = {0ull, 0ull}, a3[2] = {0ull, 0ull};

        // interleave two chunks per iteration: 4 independent LDG.128 streams
        int c = 0;
        for (; c + 2 <= nc; c += 2) {
            int idxA = g_src_sorted[e0 + c * 32 + lane];
            int idxB = g_src_sorted[e0 + (c + 1) * 32 + lane];
            #pragma unroll
            for (int j = 0; j < 32; j += 2) {
                int sA0 = __shfl_sync(0xffffffffu, idxA, j);
                int sA1 = __shfl_sync(0xffffffffu, idxA, j + 1);
                int sB0 = __shfl_sync(0xffffffffu, idxB, j);
                int sB1 = __shfl_sync(0xffffffffu, idxB, j + 1);
                ulonglong2 vA0 = *(const ulonglong2*)&x[sA0 * D + 4 * lane];
                ulonglong2 vA1 = *(const ulonglong2*)&x[sA1 * D + 4 * lane];
                ulonglong2 vB0 = *(const ulonglong2*)&x[sB0 * D + 4 * lane];
                ulonglong2 vB1 = *(const ulonglong2*)&x[sB1 * D + 4 * lane];
                fadd2(a0[0], vA0.x); fadd2(a0[1], vA0.y);
                fadd2(a1[0], vA1.x); fadd2(a1[1], vA1.y);
                fadd2(a2[0], vB0.x); fadd2(a2[1], vB0.y);
                fadd2(a3[0], vB1.x); fadd2(a3[1], vB1.y);
            }
        }
        if (c < nc) {                           // one leftover full chunk
            int idx = g_src_sorted[e0 + c * 32 + lane];
            consume_chunk(x, idx, lane, a0, a1);
            c++;
        }
        int rem = deg & 31;                     // tail < 32 edges
        if (rem > 0) {
            int base = e0 + nc * 32;
            int idx = g_src_sorted[base + ((lane < rem) ? lane : 0)];
            for (int j = 0; j < rem; j++) {
                int s = __shfl_sync(0xffffffffu, idx, j);
                ulonglong2 v = *(const ulonglong2*)&x[s * D + 4 * lane];
                fadd2(a2[0], v.x); fadd2(a2[1], v.y);
            }
        }

        fadd2(a0[0], a1[0]); fadd2(a0[1], a1[1]);
        fadd2(a2[0], a3[0]); fadd2(a2[1], a3[1]);
        fadd2(a0[0], a2[0]); fadd2(a0[1], a2[1]);
        *(ulonglong2*)&hbuf[4 * lane] = make_ulonglong2(a0[0], a0[1]);
        __syncwarp();

        // ---- projection: out[n, 4*lane..] = b + h @ Wt, f32x2 FFMA ----
        unsigned long long o0 = bb.x, o1 = bb.y;
        #pragma unroll 8
        for (int i4 = 0; i4 < D / 4; i4++) {
            float hh[4];
            *(float4*)hh = *(const float4*)&hbuf[i4 * 4];   // LDS broadcast
            #pragma unroll
            for (int k = 0; k < 4; k++) {
                ulonglong2 w2 = *(const ulonglong2*)&sW[(i4 * 4 + k) * SW_STRIDE + 4 * lane];
                unsigned long long h2 = pack2(hh[k]);
                ffma2(o0, h2, w2.x);
                ffma2(o1, h2, w2.y);
            }
        }
        *(ulonglong2*)&out[n * D + 4 * lane] = make_ulonglong2(o0, o1);
        __syncwarp();

        n = next;
    }
}

// ---------------------------------------------------------------------------
extern "C" void kernel_launch(void* const* d_in, const int* in_sizes, int n_in,
                              void* d_out, int out_size) {
    const float* x   = (const float*)d_in[0];
    const int*   src = (const int*)d_in[1];
    const int*   dst = (const int*)d_in[2];
    const float* W   = (const float*)d_in[3];
    const float* b   = (const float*)d_in[4];
    float* out = (float*)d_out;

    cudaFuncSetAttribute(fused_agg_proj_kernel,
                         cudaFuncAttributeMaxDynamicSharedMemorySize,
                         SMEM_BYTES);

    zero_deg_kernel<<<(N_NODES + 255) / 256, 256>>>();
    rank_hist_kernel<<<(N_EDGES / 2 + 255) / 256, 256>>>(dst);
    scan_kernel<<<1, 1024>>>();
    scatter_kernel<<<(N_EDGES / 2 + 255) / 256, 256>>>(src, dst);
    fused_agg_proj_kernel<<<296, 1024, SMEM_BYTES>>>(x, W, b, out);
}

// round 12
// speedup vs baseline: 1.3367x; 1.3367x over previous
#include <cuda_runtime.h>
#include <cuda_bf16.h>

#define N_NODES 10000
#define N_EDGES 640000
#define D 128

// ---- scratch (no device allocations allowed) ----
__device__ int   g_deg[N_NODES];
__device__ int   g_off[N_NODES + 1];
__device__ int   g_rank[N_EDGES];
__device__ int   g_src_sorted[N_EDGES];
__device__ int   g_work;
__device__ float g_h[N_NODES * D];     // aggregated features (5.12 MB)

// ---- f32x2 packed helpers (sm_10x; ptxas won't emit these from C++) ----
__device__ __forceinline__ void fadd2(unsigned long long& acc, unsigned long long v) {
    asm("add.rn.f32x2 %0, %0, %1;" : "+l"(acc) : "l"(v));
}
__device__ __forceinline__ void ffma2(unsigned long long& acc,
                                      unsigned long long a, unsigned long long b) {
    asm("fma.rn.f32x2 %0, %1, %2, %0;" : "+l"(acc) : "l"(a), "l"(b));
}
__device__ __forceinline__ unsigned long long pack2(float h) {
    unsigned long long r;
    asm("mov.b64 %0, {%1, %1};" : "=l"(r) : "f"(h));
    return r;
}

// ---------------------------------------------------------------------------
// 1) histogram of dst WITH per-edge rank. ILP 2, 320K threads.
//    g_deg is zero on entry (zero-init at load; re-zeroed by scan_kernel).
__global__ void rank_hist_kernel(const int* __restrict__ dst) {
    const int T = N_EDGES / 2;
    int t = blockIdx.x * blockDim.x + threadIdx.x;
    if (t >= T) return;
    int2 d2 = ((const int2*)dst)[t];
    int r0 = atomicAdd(&g_deg[d2.x], 1);
    int r1 = atomicAdd(&g_deg[d2.y], 1);
    ((int2*)g_rank)[t] = make_int2(r0, r1);
}

// 2) single-block exclusive scan; also zeroes g_deg for the next replay,
//    resets the work counter, writes the sentinel offset.
__global__ void scan_kernel() {
    __shared__ int warp_sums[32];
    const int t = threadIdx.x;
    const int lane = t & 31, w = t >> 5;
    const int CHUNK = (N_NODES + 1023) / 1024;  // 10
    const int base = t * CHUNK;

    int deg[CHUNK];
    int s = 0;
    #pragma unroll
    for (int i = 0; i < CHUNK; i++) {
        int n = base + i;
        deg[i] = (n < N_NODES) ? g_deg[n] : 0;
        if (n < N_NODES) g_deg[n] = 0;          // reset for next replay
        s += deg[i];
    }
    int incl = s;
    #pragma unroll
    for (int d = 1; d < 32; d <<= 1) {
        int v = __shfl_up_sync(0xffffffffu, incl, d);
        if (lane >= d) incl += v;
    }
    if (lane == 31) warp_sums[w] = incl;
    __syncthreads();
    if (w == 0) {
        int iv = warp_sums[lane];
        #pragma unroll
        for (int d = 1; d < 32; d <<= 1) {
            int u = __shfl_up_sync(0xffffffffu, iv, d);
            if (lane >= d) iv += u;
        }
        warp_sums[lane] = iv;
    }
    __syncthreads();
    int run = ((w > 0) ? warp_sums[w - 1] : 0) + (incl - s);
    #pragma unroll
    for (int i = 0; i < CHUNK; i++) {
        int n = base + i;
        if (n < N_NODES) {
            g_off[n] = run;
            run += deg[i];
        }
    }
    if (t == 1023) { g_off[N_NODES] = N_EDGES; g_work = 0; }
}

// 3) scatter edges — no atomics: pos = off[dst] + rank. ILP 2.
__global__ void scatter_kernel(const int* __restrict__ src,
                               const int* __restrict__ dst) {
    const int T = N_EDGES / 2;
    int t = blockIdx.x * blockDim.x + threadIdx.x;
    if (t >= T) return;
    int2 s2 = ((const int2*)src)[t];
    int2 d2 = ((const int2*)dst)[t];
    int2 r2 = ((const int2*)g_rank)[t];
    int o0 = __ldg(&g_off[d2.x]);
    int o1 = __ldg(&g_off[d2.y]);
    g_src_sorted[o0 + r2.x] = s2.x;
    g_src_sorted[o1 + r2.y] = s2.y;
}

// ---------------------------------------------------------------------------
// 4) GATHER-ONLY kernel: zero smem, low regs -> RF-limited occupancy ~40+
//    warps/SM. Warp-per-node work stealing; two interleaved 32-edge chunks
//    with cross-iteration index prefetch; h written to g_h.
__device__ __forceinline__ int steal(int lane) {
    int p = 0;
    if (lane == 0) p = atomicAdd(&g_work, 1);
    return __shfl_sync(0xffffffffu, p, 0);
}

__global__ __launch_bounds__(256)
void gather_kernel(const float* __restrict__ x) {
    const int lane = threadIdx.x & 31;

    int n = steal(lane);
    while (n < N_NODES) {
        int next = steal(lane);                 // prefetch next work unit

        const int e0  = __ldg(&g_off[n]);
        const int e1  = __ldg(&g_off[n + 1]);
        const int deg = e1 - e0;
        const int nc  = deg >> 5;

        unsigned long long a0[2] = {0ull, 0ull}, a1[2] = {0ull, 0ull};
        unsigned long long a2[2] = {0ull, 0ull}, a3[2] = {0ull, 0ull};

        int c = 0;
        if (nc >= 2) {
            int idxA = g_src_sorted[e0 + lane];
            int idxB = g_src_sorted[e0 + 32 + lane];
            for (c = 0; c + 2 <= nc; c += 2) {
                int idxA_n = 0, idxB_n = 0;
                if (c + 4 <= nc) {              // prefetch next chunk pair
                    idxA_n = g_src_sorted[e0 + (c + 2) * 32 + lane];
                    idxB_n = g_src_sorted[e0 + (c + 3) * 32 + lane];
                }
                #pragma unroll
                for (int j = 0; j < 32; j += 2) {
                    int sA0 = __shfl_sync(0xffffffffu, idxA, j);
                    int sA1 = __shfl_sync(0xffffffffu, idxA, j + 1);
                    int sB0 = __shfl_sync(0xffffffffu, idxB, j);
                    int sB1 = __shfl_sync(0xffffffffu, idxB, j + 1);
                    ulonglong2 vA0 = *(const ulonglong2*)&x[sA0 * D + 4 * lane];
                    ulonglong2 vA1 = *(const ulonglong2*)&x[sA1 * D + 4 * lane];
                    ulonglong2 vB0 = *(const ulonglong2*)&x[sB0 * D + 4 * lane];
                    ulonglong2 vB1 = *(const ulonglong2*)&x[sB1 * D + 4 * lane];
                    fadd2(a0[0], vA0.x); fadd2(a0[1], vA0.y);
                    fadd2(a1[0], vA1.x); fadd2(a1[1], vA1.y);
                    fadd2(a2[0], vB0.x); fadd2(a2[1], vB0.y);
                    fadd2(a3[0], vB1.x); fadd2(a3[1], vB1.y);
                }
                idxA = idxA_n; idxB = idxB_n;
            }
        }
        if (c < nc) {                           // one leftover full chunk
            int idx = g_src_sorted[e0 + c * 32 + lane];
            #pragma unroll
            for (int j = 0; j < 32; j += 2) {
                int s0 = __shfl_sync(0xffffffffu, idx, j);
                int s1 = __shfl_sync(0xffffffffu, idx, j + 1);
                ulonglong2 v0 = *(const ulonglong2*)&x[s0 * D + 4 * lane];
                ulonglong2 v1 = *(const ulonglong2*)&x[s1 * D + 4 * lane];
                fadd2(a0[0], v0.x); fadd2(a0[1], v0.y);
                fadd2(a1[0], v1.x); fadd2(a1[1], v1.y);
            }
        }
        int rem = deg & 31;                     // tail < 32 edges
        if (rem > 0) {
            int base = e0 + nc * 32;
            int idx = g_src_sorted[base + ((lane < rem) ? lane : 0)];
            for (int j = 0; j < rem; j++) {
                int s = __shfl_sync(0xffffffffu, idx, j);
                ulonglong2 v = *(const ulonglong2*)&x[s * D + 4 * lane];
                fadd2(a2[0], v.x); fadd2(a2[1], v.y);
            }
        }

        fadd2(a0[0], a1[0]); fadd2(a0[1], a1[1]);
        fadd2(a2[0], a3[0]); fadd2(a2[1], a3[1]);
        fadd2(a0[0], a2[0]); fadd2(a0[1], a2[1]);
        *(ulonglong2*)&g_h[n * D + 4 * lane] = make_ulonglong2(a0[0], a0[1]);

        n = next;
    }
}

// ---------------------------------------------------------------------------
// 5) PROJECTION kernel: out = h @ W^T + b. 4-node register-blocked warps,
//    sW in smem (66KB -> 3 blocks/SM), h rows read via gmem broadcast (L1).
#define SW_STRIDE 132
#define SW_FLOATS (D * SW_STRIDE)
#define SMEM_BYTES (SW_FLOATS * 4)              // 67584 B
#define NG4 (N_NODES / 4)                       // 2500 groups

__global__ __launch_bounds__(256)
void proj_kernel(const float* __restrict__ W,
                 const float* __restrict__ b,
                 float* __restrict__ out) {
    extern __shared__ float sW[];               // [128][132] transposed W

    const int tid  = threadIdx.x;
    const int lane = tid & 31;
    const int wid  = tid >> 5;

    for (int idx = tid; idx < D * D; idx += 256) {
        int o = idx >> 7;
        int i = idx & 127;
        sW[i * SW_STRIDE + o] = W[idx];
    }
    __syncthreads();

    const int g = blockIdx.x * 8 + wid;
    if (g >= NG4) return;
    const int n0 = g * 4;

    const ulonglong2 bb = *(const ulonglong2*)&b[4 * lane];
    unsigned long long oA0 = bb.x, oA1 = bb.y;
    unsigned long long oB0 = bb.x, oB1 = bb.y;
    unsigned long long oC0 = bb.x, oC1 = bb.y;
    unsigned long long oD0 = bb.x, oD1 = bb.y;

    const float* hA = &g_h[(n0 + 0) * D];
    const float* hB = &g_h[(n0 + 1) * D];
    const float* hC = &g_h[(n0 + 2) * D];
    const float* hD = &g_h[(n0 + 3) * D];

    #pragma unroll 8
    for (int i4 = 0; i4 < D / 4; i4++) {
        float ha[4], hb_[4], hc[4], hd[4];
        *(float4*)ha  = __ldg((const float4*)&hA[i4 * 4]);  // lane-uniform: 1 sector
        *(float4*)hb_ = __ldg((const float4*)&hB[i4 * 4]);
        *(float4*)hc  = __ldg((const float4*)&hC[i4 * 4]);
        *(float4*)hd  = __ldg((const float4*)&hD[i4 * 4]);
        #pragma unroll
        for (int k = 0; k < 4; k++) {
            ulonglong2 w2 = *(const ulonglong2*)&sW[(i4 * 4 + k) * SW_STRIDE + 4 * lane];
            unsigned long long a2 = pack2(ha[k]);
            unsigned long long b2 = pack2(hb_[k]);
            unsigned long long c2 = pack2(hc[k]);
            unsigned long long d2 = pack2(hd[k]);
            ffma2(oA0, a2, w2.x); ffma2(oA1, a2, w2.y);
            ffma2(oB0, b2, w2.x); ffma2(oB1, b2, w2.y);
            ffma2(oC0, c2, w2.x); ffma2(oC1, c2, w2.y);
            ffma2(oD0, d2, w2.x); ffma2(oD1, d2, w2.y);
        }
    }

    *(ulonglong2*)&out[(n0 + 0) * D + 4 * lane] = make_ulonglong2(oA0, oA1);
    *(ulonglong2*)&out[(n0 + 1) * D + 4 * lane] = make_ulonglong2(oB0, oB1);
    *(ulonglong2*)&out[(n0 + 2) * D + 4 * lane] = make_ulonglong2(oC0, oC1);
    *(ulonglong2*)&out[(n0 + 3) * D + 4 * lane] = make_ulonglong2(oD0, oD1);
}

// ---------------------------------------------------------------------------
extern "C" void kernel_launch(void* const* d_in, const int* in_sizes, int n_in,
                              void* d_out, int out_size) {
    const float* x   = (const float*)d_in[0];
    const int*   src = (const int*)d_in[1];
    const int*   dst = (const int*)d_in[2];
    const float* W   = (const float*)d_in[3];
    const float* b   = (const float*)d_in[4];
    float* out = (float*)d_out;

    cudaFuncSetAttribute(proj_kernel,
                         cudaFuncAttributeMaxDynamicSharedMemorySize,
                         SMEM_BYTES);

    rank_hist_kernel<<<(N_EDGES / 2 + 255) / 256, 256>>>(dst);
    scan_kernel<<<1, 1024>>>();
    scatter_kernel<<<(N_EDGES / 2 + 255) / 256, 256>>>(src, dst);
    gather_kernel<<<740, 256>>>(x);
    proj_kernel<<<(NG4 + 7) / 8, 256, SMEM_BYTES>>>(W, b, out);
}